// round 8
// baseline (speedup 1.0000x reference)
#include <cuda_runtime.h>
#include <cuda_bf16.h>

// LiDAR volume renderer, fused, FFMA2 (packed f32x2), 2 steps per lane.
// N=8192 rays, S=512 steps, H=32, OUT=2. One warp per ray.
// R6: density layer fused into the Wc GEMV (h never fully materialized)
//     -> ~56 fewer live regs -> __launch_bounds__(128,4), 16 warps/SM.
//
// Fusions:
//   WcExt rows 0..31 = Wfeat @ Wa1[6:22]   (precomputed per launch)
//   WcExt rows 32..34 = Wa1[0:3] (xyz rows; "h" for them is x,y,z splats)
//   b1t  = b1 + t * W1[3]
//   dirb = ba1 + rd @ Wa1[3:6] (per ray)

#define CHUNKS 8

typedef unsigned long long u64;

__device__ float g_Wc[35 * 32];
__device__ float g_b1t[32];

// ---------------------------------------------------------------------------
__global__ void lidar_precompute_kernel(const float* __restrict__ W1,
                                        const float* __restrict__ b1,
                                        const float* __restrict__ timep,
                                        const float* __restrict__ Wfeat,
                                        const float* __restrict__ Wa1) {
    int i = threadIdx.x;          // 0..1023
    int r = i >> 5;
    int c = i & 31;
    float acc = 0.f;
#pragma unroll
    for (int k = 0; k < 16; k++)
        acc = fmaf(Wfeat[r * 16 + k], Wa1[(6 + k) * 32 + c], acc);
    g_Wc[i] = acc;
    if (i < 96)                       // rows 32..34 = Wa1 rows 0..2 (xyz)
        g_Wc[1024 + i] = Wa1[i];
    if (i < 32)
        g_b1t[i] = fmaf(timep[0], W1[3 * 32 + i], b1[i]);
}

// ---------------------------------------------------------------------------
// packed f32x2 helpers
// ---------------------------------------------------------------------------
__device__ __forceinline__ u64 pk2(float a, float b) {
    u64 r; asm("mov.b64 %0,{%1,%2};" : "=l"(r) : "f"(a), "f"(b)); return r;
}
__device__ __forceinline__ float2 up2(u64 v) {
    float2 f; asm("mov.b64 {%0,%1},%2;" : "=f"(f.x), "=f"(f.y) : "l"(v)); return f;
}
__device__ __forceinline__ u64 ffma2(u64 a, u64 b, u64 c) {
    u64 d; asm("fma.rn.f32x2 %0,%1,%2,%3;" : "=l"(d) : "l"(a), "l"(b), "l"(c)); return d;
}
__device__ __forceinline__ void lds16(unsigned a, u64& p0, u64& p1) {
    asm volatile("ld.shared.v2.b64 {%0,%1},[%2];" : "=l"(p0), "=l"(p1) : "r"(a));
}
__device__ __forceinline__ u64 relu2(u64 v) {
    float2 f = up2(v);
    return pk2(fmaxf(f.x, 0.f), fmaxf(f.y, 0.f));
}

// smem layout: BYTE offsets, each 32-float block is 128B
#define O_W1R0  0u
#define O_W1R1  128u
#define O_W1R2  256u
#define O_B1T   384u
#define O_WSIG  512u
#define O_WA2A  640u
#define O_WA2B  768u
#define O_BA1   896u
#define O_WD0   1024u
#define O_WD1   1152u
#define O_WD2   1280u
#define O_WC    1408u          // 35 rows x 128B = 4480 bytes
#define O_DIRB  5888u          // 4 warps x 128B
#define SMEM_FLOATS ((5888u + 512u) / 4u)

// ---------------------------------------------------------------------------
// Main kernel: one warp per ray, 4 warps / block, 4 blocks / SM target.
// ---------------------------------------------------------------------------
__global__ __launch_bounds__(128, 4)
void lidar_render(const float* __restrict__ rays_o,
                  const float* __restrict__ rays_d,
                  const float* __restrict__ W1,
                  const float* __restrict__ Wsig,
                  const float* __restrict__ Wa1,
                  const float* __restrict__ ba1,
                  const float* __restrict__ Wa2,
                  float* __restrict__ out, int N) {
    __shared__ __align__(16) float smf[SMEM_FLOATS];

    const int tid = threadIdx.x;
    if (tid < 32) {
        smf[O_W1R0 / 4 + tid] = W1[tid];
        smf[O_W1R1 / 4 + tid] = W1[32 + tid];
        smf[O_W1R2 / 4 + tid] = W1[64 + tid];
        smf[O_B1T  / 4 + tid] = g_b1t[tid];
        smf[O_WSIG / 4 + tid] = Wsig[tid];
        smf[O_WD0  / 4 + tid] = Wa1[96 + tid];
        smf[O_WD1  / 4 + tid] = Wa1[128 + tid];
        smf[O_WD2  / 4 + tid] = Wa1[160 + tid];
        smf[O_BA1  / 4 + tid] = ba1[tid];
        smf[O_WA2A / 4 + tid] = Wa2[tid * 2 + 0];
        smf[O_WA2B / 4 + tid] = Wa2[tid * 2 + 1];
    }
    for (int i = tid; i < 35 * 32; i += 128)
        smf[O_WC / 4 + i] = g_Wc[i];
    __syncthreads();

    const int warp = tid >> 5;
    const int lane = tid & 31;
    const int ray  = blockIdx.x * 4 + warp;
    if (ray >= N) return;

    const float ox = rays_o[ray * 3 + 0];
    const float oy = rays_o[ray * 3 + 1];
    const float oz = rays_o[ray * 3 + 2];
    const float dx = rays_d[ray * 3 + 0];
    const float dy = rays_d[ray * 3 + 1];
    const float dz = rays_d[ray * 3 + 2];

    // per-ray attr bias: ba1 + rd @ Wa1[3:6]
    smf[O_DIRB / 4 + warp * 32 + lane] = smf[O_BA1 / 4 + lane]
        + dx * smf[O_WD0 / 4 + lane] + dy * smf[O_WD1 / 4 + lane]
        + dz * smf[O_WD2 / 4 + lane];
    __syncwarp();

    const unsigned base  = (unsigned)__cvta_generic_to_shared(smf);
    const unsigned bdirb = base + O_DIRB + warp * 128;

    const float ZSTEP = 0.8f / 511.f;
    float Tcarry = 1.f;
    float depth = 0.f, img0 = 0.f, img1 = 0.f, wsum = 0.f;

#pragma unroll 1
    for (int chunk = 0; chunk < CHUNKS; chunk++) {
        const int   sA = chunk * 64 + lane;
        const int   sB = sA + 32;
        const float zA = fmaf(ZSTEP, (float)sA, 0.01f);
        const float zB = fmaf(ZSTEP, (float)sB, 0.01f);
        const float xA  = fminf(fmaxf(fmaf(dx, zA, ox), -1.f), 1.f);
        const float yA  = fminf(fmaxf(fmaf(dy, zA, oy), -1.f), 1.f);
        const float zcA = fminf(fmaxf(fmaf(dz, zA, oz), -1.f), 1.f);
        const float xB  = fminf(fmaxf(fmaf(dx, zB, ox), -1.f), 1.f);
        const float yB  = fminf(fmaxf(fmaf(dy, zB, oy), -1.f), 1.f);
        const float zcB = fminf(fmaxf(fmaf(dz, zB, oz), -1.f), 1.f);

        const u64 xxA = pk2(xA, xA), yyA = pk2(yA, yA), zzA = pk2(zcA, zcA);
        const u64 xxB = pk2(xB, xB), yyB = pk2(yB, yB), zzB = pk2(zcB, zcB);

        // --- attr acc init from per-ray bias ---
        u64 accA[16], accB[16];
#pragma unroll
        for (int k = 0; k < 8; k++) {
            u64 da, db;
            lds16(bdirb + k * 16, da, db);
            accA[2*k+0] = da; accA[2*k+1] = db;
            accB[2*k+0] = da; accB[2*k+1] = db;
        }

        // one Wc GEMV row: acc{A,B} += splat{A,B} * Wc[j][:]
#define WC_ROW(J, HJA, HJB)                                                   \
        {                                                                     \
            const unsigned row = base + O_WC + (unsigned)(J) * 128u;          \
            _Pragma("unroll")                                                 \
            for (int m = 0; m < 4; m++) {                                     \
                u64 p0, p1, p2, p3;                                           \
                lds16(row + m * 32,      p0, p1);                             \
                lds16(row + m * 32 + 16, p2, p3);                             \
                accA[4*m+0] = ffma2((HJA), p0, accA[4*m+0]);                  \
                accA[4*m+1] = ffma2((HJA), p1, accA[4*m+1]);                  \
                accA[4*m+2] = ffma2((HJA), p2, accA[4*m+2]);                  \
                accA[4*m+3] = ffma2((HJA), p3, accA[4*m+3]);                  \
                accB[4*m+0] = ffma2((HJB), p0, accB[4*m+0]);                  \
                accB[4*m+1] = ffma2((HJB), p1, accB[4*m+1]);                  \
                accB[4*m+2] = ffma2((HJB), p2, accB[4*m+2]);                  \
                accB[4*m+3] = ffma2((HJB), p3, accB[4*m+3]);                  \
            }                                                                 \
        }

        // --- fused: density k-group (4 hidden units) -> 4 Wc rows ---
        u64 sgA = 0ULL, sgB = 0ULL;
#pragma unroll
        for (int k = 0; k < 8; k++) {
            u64 w0a, w0b, w1a, w1b, w2a, w2b, ba, bb, sa, sb;
            lds16(base + O_W1R0 + k * 16, w0a, w0b);
            lds16(base + O_W1R1 + k * 16, w1a, w1b);
            lds16(base + O_W1R2 + k * 16, w2a, w2b);
            lds16(base + O_B1T  + k * 16, ba, bb);
            lds16(base + O_WSIG + k * 16, sa, sb);
            const u64 vA0 = relu2(ffma2(xxA, w0a, ffma2(yyA, w1a, ffma2(zzA, w2a, ba))));
            const u64 vA1 = relu2(ffma2(xxA, w0b, ffma2(yyA, w1b, ffma2(zzA, w2b, bb))));
            const u64 vB0 = relu2(ffma2(xxB, w0a, ffma2(yyB, w1a, ffma2(zzB, w2a, ba))));
            const u64 vB1 = relu2(ffma2(xxB, w0b, ffma2(yyB, w1b, ffma2(zzB, w2b, bb))));
            sgA = ffma2(vA0, sa, sgA); sgA = ffma2(vA1, sb, sgA);
            sgB = ffma2(vB0, sa, sgB); sgB = ffma2(vB1, sb, sgB);

            const float2 fA0 = up2(vA0), fA1 = up2(vA1);
            const float2 fB0 = up2(vB0), fB1 = up2(vB1);
            {
                const u64 hA0 = pk2(fA0.x, fA0.x), hB0 = pk2(fB0.x, fB0.x);
                WC_ROW(4 * k + 0, hA0, hB0)
            }
            {
                const u64 hA1 = pk2(fA0.y, fA0.y), hB1 = pk2(fB0.y, fB0.y);
                WC_ROW(4 * k + 1, hA1, hB1)
            }
            {
                const u64 hA2 = pk2(fA1.x, fA1.x), hB2 = pk2(fB1.x, fB1.x);
                WC_ROW(4 * k + 2, hA2, hB2)
            }
            {
                const u64 hA3 = pk2(fA1.y, fA1.y), hB3 = pk2(fB1.y, fB1.y);
                WC_ROW(4 * k + 3, hA3, hB3)
            }
        }
        WC_ROW(32, xxA, xxB)
        WC_ROW(33, yyA, yyB)
        WC_ROW(34, zzA, zzB)
#undef WC_ROW

        // --- sigma -> alpha ---
        const float2 sA2 = up2(sgA), sB2 = up2(sgB);
        const float sigA = sA2.x + sA2.y;
        const float sigB = sB2.x + sB2.y;
        const float sigmaA = fmaxf(sigA, 0.f) + __logf(1.f + __expf(-fabsf(sigA)));
        const float sigmaB = fmaxf(sigB, 0.f) + __logf(1.f + __expf(-fabsf(sigB)));
        const float deltaB = (sB == 511) ? (0.8f / 512.f) : ZSTEP;
        float qA = __expf(-ZSTEP  * sigmaA);
        float qB = __expf(-deltaB * sigmaB);
        const float alphaA = 1.f - qA;
        const float alphaB = 1.f - qB;
        qA += 1e-15f; qB += 1e-15f;

        // --- attr head: relu then @ Wa2 (both steps) ---
        u64 oA0 = 0ULL, oA1 = 0ULL, oB0 = 0ULL, oB1 = 0ULL;
#pragma unroll
        for (int k = 0; k < 8; k++) {
            u64 wa0, wa1v, wb0, wb1v;
            lds16(base + O_WA2A + k * 16, wa0, wa1v);
            lds16(base + O_WA2B + k * 16, wb0, wb1v);
            const u64 rA0 = relu2(accA[2*k+0]), rA1 = relu2(accA[2*k+1]);
            const u64 rB0 = relu2(accB[2*k+0]), rB1 = relu2(accB[2*k+1]);
            oA0 = ffma2(rA0, wa0, oA0); oA0 = ffma2(rA1, wa1v, oA0);
            oA1 = ffma2(rA0, wb0, oA1); oA1 = ffma2(rA1, wb1v, oA1);
            oB0 = ffma2(rB0, wa0, oB0); oB0 = ffma2(rB1, wa1v, oB0);
            oB1 = ffma2(rB0, wb0, oB1); oB1 = ffma2(rB1, wb1v, oB1);
        }
        const float2 tA0 = up2(oA0), tA1 = up2(oA1);
        const float2 tB0 = up2(oB0), tB1 = up2(oB1);
        const float aA0 = 1.f / (1.f + __expf(-(tA0.x + tA0.y)));
        const float aA1 = 1.f / (1.f + __expf(-(tA1.x + tA1.y)));
        const float aB0 = 1.f / (1.f + __expf(-(tB0.x + tB0.y)));
        const float aB1 = 1.f / (1.f + __expf(-(tB1.x + tB1.y)));

        // --- transmittance scans: steps A (s..s+31) then B (s+32..s+63) ---
        float PA = qA;
#pragma unroll
        for (int off = 1; off < 32; off <<= 1) {
            const float v = __shfl_up_sync(0xffffffffu, PA, off);
            if (lane >= off) PA *= v;
        }
        float PexA = __shfl_up_sync(0xffffffffu, PA, 1);
        if (lane == 0) PexA = 1.f;
        const float wA = alphaA * Tcarry * PexA;
        const float Tmid = Tcarry * __shfl_sync(0xffffffffu, PA, 31);

        float PB = qB;
#pragma unroll
        for (int off = 1; off < 32; off <<= 1) {
            const float v = __shfl_up_sync(0xffffffffu, PB, off);
            if (lane >= off) PB *= v;
        }
        float PexB = __shfl_up_sync(0xffffffffu, PB, 1);
        if (lane == 0) PexB = 1.f;
        const float wB = alphaB * Tmid * PexB;
        Tcarry = Tmid * __shfl_sync(0xffffffffu, PB, 31);

        depth = fmaf(wA, zA, fmaf(wB, zB, depth));
        img0  = fmaf(wA, aA0, fmaf(wB, aB0, img0));
        img1  = fmaf(wA, aA1, fmaf(wB, aB1, img1));
        wsum += wA + wB;
    }

    // warp reduction, lane 0 writes
#pragma unroll
    for (int off = 16; off; off >>= 1) {
        depth += __shfl_xor_sync(0xffffffffu, depth, off);
        img0  += __shfl_xor_sync(0xffffffffu, img0, off);
        img1  += __shfl_xor_sync(0xffffffffu, img1, off);
        wsum  += __shfl_xor_sync(0xffffffffu, wsum, off);
    }
    if (lane == 0) {
        out[ray]             = depth;        // depth        [N]
        out[N + ray * 2 + 0] = img0;         // image        [N,2]
        out[N + ray * 2 + 1] = img1;
        out[3 * N + ray]     = wsum;         // weights_sum  [N]
    }
}

// ---------------------------------------------------------------------------
// Launch. Inputs (metadata order):
// 0 rays_o  1 rays_d  2 time  3 W1  4 b1  5 Wsig  6 Wfeat  7 Wa1  8 ba1
// 9 Wa2  10 num_steps
// ---------------------------------------------------------------------------
extern "C" void kernel_launch(void* const* d_in, const int* in_sizes, int n_in,
                              void* d_out, int out_size) {
    const float* rays_o = (const float*)d_in[0];
    const float* rays_d = (const float*)d_in[1];
    const float* timep  = (const float*)d_in[2];
    const float* W1     = (const float*)d_in[3];
    const float* b1     = (const float*)d_in[4];
    const float* Wsig   = (const float*)d_in[5];
    const float* Wfeat  = (const float*)d_in[6];
    const float* Wa1    = (const float*)d_in[7];
    const float* ba1    = (const float*)d_in[8];
    const float* Wa2    = (const float*)d_in[9];

    const int N = in_sizes[0] / 3;   // 8192

    lidar_precompute_kernel<<<1, 1024>>>(W1, b1, timep, Wfeat, Wa1);
    lidar_render<<<(N + 3) / 4, 128>>>(rays_o, rays_d, W1, Wsig, Wa1,
                                       ba1, Wa2, (float*)d_out, N);
}

// round 9
// speedup vs baseline: 1.0547x; 1.0547x over previous
#include <cuda_runtime.h>
#include <cuda_bf16.h>

// LiDAR volume renderer, fused, FFMA2 (packed f32x2), 2 steps per lane.
// N=8192 rays, S=512 steps, H=32, OUT=2. One warp per ray.
// R6: density layer fused into the Wc GEMV (h never fully materialized)
//     -> ~56 fewer live regs -> __launch_bounds__(128,4), 16 warps/SM.
//
// Fusions:
//   WcExt rows 0..31 = Wfeat @ Wa1[6:22]   (precomputed per launch)
//   WcExt rows 32..34 = Wa1[0:3] (xyz rows; "h" for them is x,y,z splats)
//   b1t  = b1 + t * W1[3]
//   dirb = ba1 + rd @ Wa1[3:6] (per ray)

#define CHUNKS 8

typedef unsigned long long u64;

__device__ float g_Wc[35 * 32];
__device__ float g_b1t[32];

// ---------------------------------------------------------------------------
__global__ void lidar_precompute_kernel(const float* __restrict__ W1,
                                        const float* __restrict__ b1,
                                        const float* __restrict__ timep,
                                        const float* __restrict__ Wfeat,
                                        const float* __restrict__ Wa1) {
    int i = threadIdx.x;          // 0..1023
    int r = i >> 5;
    int c = i & 31;
    float acc = 0.f;
#pragma unroll
    for (int k = 0; k < 16; k++)
        acc = fmaf(Wfeat[r * 16 + k], Wa1[(6 + k) * 32 + c], acc);
    g_Wc[i] = acc;
    if (i < 96)                       // rows 32..34 = Wa1 rows 0..2 (xyz)
        g_Wc[1024 + i] = Wa1[i];
    if (i < 32)
        g_b1t[i] = fmaf(timep[0], W1[3 * 32 + i], b1[i]);
}

// ---------------------------------------------------------------------------
// packed f32x2 helpers
// ---------------------------------------------------------------------------
__device__ __forceinline__ u64 pk2(float a, float b) {
    u64 r; asm("mov.b64 %0,{%1,%2};" : "=l"(r) : "f"(a), "f"(b)); return r;
}
__device__ __forceinline__ float2 up2(u64 v) {
    float2 f; asm("mov.b64 {%0,%1},%2;" : "=f"(f.x), "=f"(f.y) : "l"(v)); return f;
}
__device__ __forceinline__ u64 ffma2(u64 a, u64 b, u64 c) {
    u64 d; asm("fma.rn.f32x2 %0,%1,%2,%3;" : "=l"(d) : "l"(a), "l"(b), "l"(c)); return d;
}
__device__ __forceinline__ void lds16(unsigned a, u64& p0, u64& p1) {
    asm volatile("ld.shared.v2.b64 {%0,%1},[%2];" : "=l"(p0), "=l"(p1) : "r"(a));
}
__device__ __forceinline__ u64 relu2(u64 v) {
    float2 f = up2(v);
    return pk2(fmaxf(f.x, 0.f), fmaxf(f.y, 0.f));
}

// smem layout: BYTE offsets, each 32-float block is 128B
#define O_W1R0  0u
#define O_W1R1  128u
#define O_W1R2  256u
#define O_B1T   384u
#define O_WSIG  512u
#define O_WA2A  640u
#define O_WA2B  768u
#define O_BA1   896u
#define O_WD0   1024u
#define O_WD1   1152u
#define O_WD2   1280u
#define O_WC    1408u          // 35 rows x 128B = 4480 bytes
#define O_DIRB  5888u          // 4 warps x 128B
#define SMEM_FLOATS ((5888u + 512u) / 4u)

// ---------------------------------------------------------------------------
// Main kernel: one warp per ray, 4 warps / block, 4 blocks / SM target.
// ---------------------------------------------------------------------------
__global__ __launch_bounds__(128, 4)
void lidar_render(const float* __restrict__ rays_o,
                  const float* __restrict__ rays_d,
                  const float* __restrict__ W1,
                  const float* __restrict__ Wsig,
                  const float* __restrict__ Wa1,
                  const float* __restrict__ ba1,
                  const float* __restrict__ Wa2,
                  float* __restrict__ out, int N) {
    __shared__ __align__(16) float smf[SMEM_FLOATS];

    const int tid = threadIdx.x;
    if (tid < 32) {
        smf[O_W1R0 / 4 + tid] = W1[tid];
        smf[O_W1R1 / 4 + tid] = W1[32 + tid];
        smf[O_W1R2 / 4 + tid] = W1[64 + tid];
        smf[O_B1T  / 4 + tid] = g_b1t[tid];
        smf[O_WSIG / 4 + tid] = Wsig[tid];
        smf[O_WD0  / 4 + tid] = Wa1[96 + tid];
        smf[O_WD1  / 4 + tid] = Wa1[128 + tid];
        smf[O_WD2  / 4 + tid] = Wa1[160 + tid];
        smf[O_BA1  / 4 + tid] = ba1[tid];
        smf[O_WA2A / 4 + tid] = Wa2[tid * 2 + 0];
        smf[O_WA2B / 4 + tid] = Wa2[tid * 2 + 1];
    }
    for (int i = tid; i < 35 * 32; i += 128)
        smf[O_WC / 4 + i] = g_Wc[i];
    __syncthreads();

    const int warp = tid >> 5;
    const int lane = tid & 31;
    const int ray  = blockIdx.x * 4 + warp;
    if (ray >= N) return;

    const float ox = rays_o[ray * 3 + 0];
    const float oy = rays_o[ray * 3 + 1];
    const float oz = rays_o[ray * 3 + 2];
    const float dx = rays_d[ray * 3 + 0];
    const float dy = rays_d[ray * 3 + 1];
    const float dz = rays_d[ray * 3 + 2];

    // per-ray attr bias: ba1 + rd @ Wa1[3:6]
    smf[O_DIRB / 4 + warp * 32 + lane] = smf[O_BA1 / 4 + lane]
        + dx * smf[O_WD0 / 4 + lane] + dy * smf[O_WD1 / 4 + lane]
        + dz * smf[O_WD2 / 4 + lane];
    __syncwarp();

    const unsigned base  = (unsigned)__cvta_generic_to_shared(smf);
    const unsigned bdirb = base + O_DIRB + warp * 128;

    const float ZSTEP = 0.8f / 511.f;
    float Tcarry = 1.f;
    float depth = 0.f, img0 = 0.f, img1 = 0.f, wsum = 0.f;

#pragma unroll 1
    for (int chunk = 0; chunk < CHUNKS; chunk++) {
        const int   sA = chunk * 64 + lane;
        const int   sB = sA + 32;
        const float zA = fmaf(ZSTEP, (float)sA, 0.01f);
        const float zB = fmaf(ZSTEP, (float)sB, 0.01f);
        const float xA  = fminf(fmaxf(fmaf(dx, zA, ox), -1.f), 1.f);
        const float yA  = fminf(fmaxf(fmaf(dy, zA, oy), -1.f), 1.f);
        const float zcA = fminf(fmaxf(fmaf(dz, zA, oz), -1.f), 1.f);
        const float xB  = fminf(fmaxf(fmaf(dx, zB, ox), -1.f), 1.f);
        const float yB  = fminf(fmaxf(fmaf(dy, zB, oy), -1.f), 1.f);
        const float zcB = fminf(fmaxf(fmaf(dz, zB, oz), -1.f), 1.f);

        const u64 xxA = pk2(xA, xA), yyA = pk2(yA, yA), zzA = pk2(zcA, zcA);
        const u64 xxB = pk2(xB, xB), yyB = pk2(yB, yB), zzB = pk2(zcB, zcB);

        // --- attr acc init from per-ray bias ---
        u64 accA[16], accB[16];
#pragma unroll
        for (int k = 0; k < 8; k++) {
            u64 da, db;
            lds16(bdirb + k * 16, da, db);
            accA[2*k+0] = da; accA[2*k+1] = db;
            accB[2*k+0] = da; accB[2*k+1] = db;
        }

        // one Wc GEMV row: acc{A,B} += splat{A,B} * Wc[j][:]
#define WC_ROW(J, HJA, HJB)                                                   \
        {                                                                     \
            const unsigned row = base + O_WC + (unsigned)(J) * 128u;          \
            _Pragma("unroll")                                                 \
            for (int m = 0; m < 4; m++) {                                     \
                u64 p0, p1, p2, p3;                                           \
                lds16(row + m * 32,      p0, p1);                             \
                lds16(row + m * 32 + 16, p2, p3);                             \
                accA[4*m+0] = ffma2((HJA), p0, accA[4*m+0]);                  \
                accA[4*m+1] = ffma2((HJA), p1, accA[4*m+1]);                  \
                accA[4*m+2] = ffma2((HJA), p2, accA[4*m+2]);                  \
                accA[4*m+3] = ffma2((HJA), p3, accA[4*m+3]);                  \
                accB[4*m+0] = ffma2((HJB), p0, accB[4*m+0]);                  \
                accB[4*m+1] = ffma2((HJB), p1, accB[4*m+1]);                  \
                accB[4*m+2] = ffma2((HJB), p2, accB[4*m+2]);                  \
                accB[4*m+3] = ffma2((HJB), p3, accB[4*m+3]);                  \
            }                                                                 \
        }

        // --- fused: density k-group (4 hidden units) -> 4 Wc rows ---
        u64 sgA = 0ULL, sgB = 0ULL;
#pragma unroll
        for (int k = 0; k < 8; k++) {
            u64 w0a, w0b, w1a, w1b, w2a, w2b, ba, bb, sa, sb;
            lds16(base + O_W1R0 + k * 16, w0a, w0b);
            lds16(base + O_W1R1 + k * 16, w1a, w1b);
            lds16(base + O_W1R2 + k * 16, w2a, w2b);
            lds16(base + O_B1T  + k * 16, ba, bb);
            lds16(base + O_WSIG + k * 16, sa, sb);
            const u64 vA0 = relu2(ffma2(xxA, w0a, ffma2(yyA, w1a, ffma2(zzA, w2a, ba))));
            const u64 vA1 = relu2(ffma2(xxA, w0b, ffma2(yyA, w1b, ffma2(zzA, w2b, bb))));
            const u64 vB0 = relu2(ffma2(xxB, w0a, ffma2(yyB, w1a, ffma2(zzB, w2a, ba))));
            const u64 vB1 = relu2(ffma2(xxB, w0b, ffma2(yyB, w1b, ffma2(zzB, w2b, bb))));
            sgA = ffma2(vA0, sa, sgA); sgA = ffma2(vA1, sb, sgA);
            sgB = ffma2(vB0, sa, sgB); sgB = ffma2(vB1, sb, sgB);

            const float2 fA0 = up2(vA0), fA1 = up2(vA1);
            const float2 fB0 = up2(vB0), fB1 = up2(vB1);
            {
                const u64 hA0 = pk2(fA0.x, fA0.x), hB0 = pk2(fB0.x, fB0.x);
                WC_ROW(4 * k + 0, hA0, hB0)
            }
            {
                const u64 hA1 = pk2(fA0.y, fA0.y), hB1 = pk2(fB0.y, fB0.y);
                WC_ROW(4 * k + 1, hA1, hB1)
            }
            {
                const u64 hA2 = pk2(fA1.x, fA1.x), hB2 = pk2(fB1.x, fB1.x);
                WC_ROW(4 * k + 2, hA2, hB2)
            }
            {
                const u64 hA3 = pk2(fA1.y, fA1.y), hB3 = pk2(fB1.y, fB1.y);
                WC_ROW(4 * k + 3, hA3, hB3)
            }
        }
        WC_ROW(32, xxA, xxB)
        WC_ROW(33, yyA, yyB)
        WC_ROW(34, zzA, zzB)
#undef WC_ROW

        // --- sigma -> alpha ---
        const float2 sA2 = up2(sgA), sB2 = up2(sgB);
        const float sigA = sA2.x + sA2.y;
        const float sigB = sB2.x + sB2.y;
        const float sigmaA = fmaxf(sigA, 0.f) + __logf(1.f + __expf(-fabsf(sigA)));
        const float sigmaB = fmaxf(sigB, 0.f) + __logf(1.f + __expf(-fabsf(sigB)));
        const float deltaB = (sB == 511) ? (0.8f / 512.f) : ZSTEP;
        float qA = __expf(-ZSTEP  * sigmaA);
        float qB = __expf(-deltaB * sigmaB);
        const float alphaA = 1.f - qA;
        const float alphaB = 1.f - qB;
        qA += 1e-15f; qB += 1e-15f;

        // --- attr head: relu then @ Wa2 (both steps) ---
        u64 oA0 = 0ULL, oA1 = 0ULL, oB0 = 0ULL, oB1 = 0ULL;
#pragma unroll
        for (int k = 0; k < 8; k++) {
            u64 wa0, wa1v, wb0, wb1v;
            lds16(base + O_WA2A + k * 16, wa0, wa1v);
            lds16(base + O_WA2B + k * 16, wb0, wb1v);
            const u64 rA0 = relu2(accA[2*k+0]), rA1 = relu2(accA[2*k+1]);
            const u64 rB0 = relu2(accB[2*k+0]), rB1 = relu2(accB[2*k+1]);
            oA0 = ffma2(rA0, wa0, oA0); oA0 = ffma2(rA1, wa1v, oA0);
            oA1 = ffma2(rA0, wb0, oA1); oA1 = ffma2(rA1, wb1v, oA1);
            oB0 = ffma2(rB0, wa0, oB0); oB0 = ffma2(rB1, wa1v, oB0);
            oB1 = ffma2(rB0, wb0, oB1); oB1 = ffma2(rB1, wb1v, oB1);
        }
        const float2 tA0 = up2(oA0), tA1 = up2(oA1);
        const float2 tB0 = up2(oB0), tB1 = up2(oB1);
        const float aA0 = 1.f / (1.f + __expf(-(tA0.x + tA0.y)));
        const float aA1 = 1.f / (1.f + __expf(-(tA1.x + tA1.y)));
        const float aB0 = 1.f / (1.f + __expf(-(tB0.x + tB0.y)));
        const float aB1 = 1.f / (1.f + __expf(-(tB1.x + tB1.y)));

        // --- transmittance scans: steps A (s..s+31) then B (s+32..s+63) ---
        float PA = qA;
#pragma unroll
        for (int off = 1; off < 32; off <<= 1) {
            const float v = __shfl_up_sync(0xffffffffu, PA, off);
            if (lane >= off) PA *= v;
        }
        float PexA = __shfl_up_sync(0xffffffffu, PA, 1);
        if (lane == 0) PexA = 1.f;
        const float wA = alphaA * Tcarry * PexA;
        const float Tmid = Tcarry * __shfl_sync(0xffffffffu, PA, 31);

        float PB = qB;
#pragma unroll
        for (int off = 1; off < 32; off <<= 1) {
            const float v = __shfl_up_sync(0xffffffffu, PB, off);
            if (lane >= off) PB *= v;
        }
        float PexB = __shfl_up_sync(0xffffffffu, PB, 1);
        if (lane == 0) PexB = 1.f;
        const float wB = alphaB * Tmid * PexB;
        Tcarry = Tmid * __shfl_sync(0xffffffffu, PB, 31);

        depth = fmaf(wA, zA, fmaf(wB, zB, depth));
        img0  = fmaf(wA, aA0, fmaf(wB, aB0, img0));
        img1  = fmaf(wA, aA1, fmaf(wB, aB1, img1));
        wsum += wA + wB;
    }

    // warp reduction, lane 0 writes
#pragma unroll
    for (int off = 16; off; off >>= 1) {
        depth += __shfl_xor_sync(0xffffffffu, depth, off);
        img0  += __shfl_xor_sync(0xffffffffu, img0, off);
        img1  += __shfl_xor_sync(0xffffffffu, img1, off);
        wsum  += __shfl_xor_sync(0xffffffffu, wsum, off);
    }
    if (lane == 0) {
        out[ray]             = depth;        // depth        [N]
        out[N + ray * 2 + 0] = img0;         // image        [N,2]
        out[N + ray * 2 + 1] = img1;
        out[3 * N + ray]     = wsum;         // weights_sum  [N]
    }
}

// ---------------------------------------------------------------------------
// Launch. Inputs (metadata order):
// 0 rays_o  1 rays_d  2 time  3 W1  4 b1  5 Wsig  6 Wfeat  7 Wa1  8 ba1
// 9 Wa2  10 num_steps
// ---------------------------------------------------------------------------
extern "C" void kernel_launch(void* const* d_in, const int* in_sizes, int n_in,
                              void* d_out, int out_size) {
    const float* rays_o = (const float*)d_in[0];
    const float* rays_d = (const float*)d_in[1];
    const float* timep  = (const float*)d_in[2];
    const float* W1     = (const float*)d_in[3];
    const float* b1     = (const float*)d_in[4];
    const float* Wsig   = (const float*)d_in[5];
    const float* Wfeat  = (const float*)d_in[6];
    const float* Wa1    = (const float*)d_in[7];
    const float* ba1    = (const float*)d_in[8];
    const float* Wa2    = (const float*)d_in[9];

    const int N = in_sizes[0] / 3;   // 8192

    lidar_precompute_kernel<<<1, 1024>>>(W1, b1, timep, Wfeat, Wa1);
    lidar_render<<<(N + 3) / 4, 128>>>(rays_o, rays_d, W1, Wsig, Wa1,
                                       ba1, Wa2, (float*)d_out, N);
}

// round 10
// speedup vs baseline: 1.0576x; 1.0027x over previous
#include <cuda_runtime.h>
#include <cuda_bf16.h>

// LiDAR volume renderer, fused, FFMA2 (packed f32x2), 2 steps per lane.
// N=8192 rays, S=512 steps, H=32, OUT=2. One warp per ray.
// R6: density layer fused into the Wc GEMV (h never fully materialized)
//     -> ~56 fewer live regs -> __launch_bounds__(128,4), 16 warps/SM.
//
// Fusions:
//   WcExt rows 0..31 = Wfeat @ Wa1[6:22]   (precomputed per launch)
//   WcExt rows 32..34 = Wa1[0:3] (xyz rows; "h" for them is x,y,z splats)
//   b1t  = b1 + t * W1[3]
//   dirb = ba1 + rd @ Wa1[3:6] (per ray)

#define CHUNKS 8

typedef unsigned long long u64;

__device__ float g_Wc[35 * 32];
__device__ float g_b1t[32];

// ---------------------------------------------------------------------------
__global__ void lidar_precompute_kernel(const float* __restrict__ W1,
                                        const float* __restrict__ b1,
                                        const float* __restrict__ timep,
                                        const float* __restrict__ Wfeat,
                                        const float* __restrict__ Wa1) {
    int i = threadIdx.x;          // 0..1023
    int r = i >> 5;
    int c = i & 31;
    float acc = 0.f;
#pragma unroll
    for (int k = 0; k < 16; k++)
        acc = fmaf(Wfeat[r * 16 + k], Wa1[(6 + k) * 32 + c], acc);
    g_Wc[i] = acc;
    if (i < 96)                       // rows 32..34 = Wa1 rows 0..2 (xyz)
        g_Wc[1024 + i] = Wa1[i];
    if (i < 32)
        g_b1t[i] = fmaf(timep[0], W1[3 * 32 + i], b1[i]);
}

// ---------------------------------------------------------------------------
// packed f32x2 helpers
// ---------------------------------------------------------------------------
__device__ __forceinline__ u64 pk2(float a, float b) {
    u64 r; asm("mov.b64 %0,{%1,%2};" : "=l"(r) : "f"(a), "f"(b)); return r;
}
__device__ __forceinline__ float2 up2(u64 v) {
    float2 f; asm("mov.b64 {%0,%1},%2;" : "=f"(f.x), "=f"(f.y) : "l"(v)); return f;
}
__device__ __forceinline__ u64 ffma2(u64 a, u64 b, u64 c) {
    u64 d; asm("fma.rn.f32x2 %0,%1,%2,%3;" : "=l"(d) : "l"(a), "l"(b), "l"(c)); return d;
}
__device__ __forceinline__ void lds16(unsigned a, u64& p0, u64& p1) {
    asm volatile("ld.shared.v2.b64 {%0,%1},[%2];" : "=l"(p0), "=l"(p1) : "r"(a));
}
__device__ __forceinline__ u64 relu2(u64 v) {
    float2 f = up2(v);
    return pk2(fmaxf(f.x, 0.f), fmaxf(f.y, 0.f));
}

// smem layout: BYTE offsets, each 32-float block is 128B
#define O_W1R0  0u
#define O_W1R1  128u
#define O_W1R2  256u
#define O_B1T   384u
#define O_WSIG  512u
#define O_WA2A  640u
#define O_WA2B  768u
#define O_BA1   896u
#define O_WD0   1024u
#define O_WD1   1152u
#define O_WD2   1280u
#define O_WC    1408u          // 35 rows x 128B = 4480 bytes
#define O_DIRB  5888u          // 4 warps x 128B
#define SMEM_FLOATS ((5888u + 512u) / 4u)

// ---------------------------------------------------------------------------
// Main kernel: one warp per ray, 4 warps / block, 4 blocks / SM target.
// ---------------------------------------------------------------------------
__global__ __launch_bounds__(128, 4)
void lidar_render(const float* __restrict__ rays_o,
                  const float* __restrict__ rays_d,
                  const float* __restrict__ W1,
                  const float* __restrict__ Wsig,
                  const float* __restrict__ Wa1,
                  const float* __restrict__ ba1,
                  const float* __restrict__ Wa2,
                  float* __restrict__ out, int N) {
    __shared__ __align__(16) float smf[SMEM_FLOATS];

    const int tid = threadIdx.x;
    if (tid < 32) {
        smf[O_W1R0 / 4 + tid] = W1[tid];
        smf[O_W1R1 / 4 + tid] = W1[32 + tid];
        smf[O_W1R2 / 4 + tid] = W1[64 + tid];
        smf[O_B1T  / 4 + tid] = g_b1t[tid];
        smf[O_WSIG / 4 + tid] = Wsig[tid];
        smf[O_WD0  / 4 + tid] = Wa1[96 + tid];
        smf[O_WD1  / 4 + tid] = Wa1[128 + tid];
        smf[O_WD2  / 4 + tid] = Wa1[160 + tid];
        smf[O_BA1  / 4 + tid] = ba1[tid];
        smf[O_WA2A / 4 + tid] = Wa2[tid * 2 + 0];
        smf[O_WA2B / 4 + tid] = Wa2[tid * 2 + 1];
    }
    for (int i = tid; i < 35 * 32; i += 128)
        smf[O_WC / 4 + i] = g_Wc[i];
    __syncthreads();

    const int warp = tid >> 5;
    const int lane = tid & 31;
    const int ray  = blockIdx.x * 4 + warp;
    if (ray >= N) return;

    const float ox = rays_o[ray * 3 + 0];
    const float oy = rays_o[ray * 3 + 1];
    const float oz = rays_o[ray * 3 + 2];
    const float dx = rays_d[ray * 3 + 0];
    const float dy = rays_d[ray * 3 + 1];
    const float dz = rays_d[ray * 3 + 2];

    // per-ray attr bias: ba1 + rd @ Wa1[3:6]
    smf[O_DIRB / 4 + warp * 32 + lane] = smf[O_BA1 / 4 + lane]
        + dx * smf[O_WD0 / 4 + lane] + dy * smf[O_WD1 / 4 + lane]
        + dz * smf[O_WD2 / 4 + lane];
    __syncwarp();

    const unsigned base  = (unsigned)__cvta_generic_to_shared(smf);
    const unsigned bdirb = base + O_DIRB + warp * 128;

    const float ZSTEP = 0.8f / 511.f;
    float Tcarry = 1.f;
    float depth = 0.f, img0 = 0.f, img1 = 0.f, wsum = 0.f;

#pragma unroll 1
    for (int chunk = 0; chunk < CHUNKS; chunk++) {
        const int   sA = chunk * 64 + lane;
        const int   sB = sA + 32;
        const float zA = fmaf(ZSTEP, (float)sA, 0.01f);
        const float zB = fmaf(ZSTEP, (float)sB, 0.01f);
        const float xA  = fminf(fmaxf(fmaf(dx, zA, ox), -1.f), 1.f);
        const float yA  = fminf(fmaxf(fmaf(dy, zA, oy), -1.f), 1.f);
        const float zcA = fminf(fmaxf(fmaf(dz, zA, oz), -1.f), 1.f);
        const float xB  = fminf(fmaxf(fmaf(dx, zB, ox), -1.f), 1.f);
        const float yB  = fminf(fmaxf(fmaf(dy, zB, oy), -1.f), 1.f);
        const float zcB = fminf(fmaxf(fmaf(dz, zB, oz), -1.f), 1.f);

        const u64 xxA = pk2(xA, xA), yyA = pk2(yA, yA), zzA = pk2(zcA, zcA);
        const u64 xxB = pk2(xB, xB), yyB = pk2(yB, yB), zzB = pk2(zcB, zcB);

        // --- attr acc init from per-ray bias ---
        u64 accA[16], accB[16];
#pragma unroll
        for (int k = 0; k < 8; k++) {
            u64 da, db;
            lds16(bdirb + k * 16, da, db);
            accA[2*k+0] = da; accA[2*k+1] = db;
            accB[2*k+0] = da; accB[2*k+1] = db;
        }

        // one Wc GEMV row: acc{A,B} += splat{A,B} * Wc[j][:]
#define WC_ROW(J, HJA, HJB)                                                   \
        {                                                                     \
            const unsigned row = base + O_WC + (unsigned)(J) * 128u;          \
            _Pragma("unroll")                                                 \
            for (int m = 0; m < 4; m++) {                                     \
                u64 p0, p1, p2, p3;                                           \
                lds16(row + m * 32,      p0, p1);                             \
                lds16(row + m * 32 + 16, p2, p3);                             \
                accA[4*m+0] = ffma2((HJA), p0, accA[4*m+0]);                  \
                accA[4*m+1] = ffma2((HJA), p1, accA[4*m+1]);                  \
                accA[4*m+2] = ffma2((HJA), p2, accA[4*m+2]);                  \
                accA[4*m+3] = ffma2((HJA), p3, accA[4*m+3]);                  \
                accB[4*m+0] = ffma2((HJB), p0, accB[4*m+0]);                  \
                accB[4*m+1] = ffma2((HJB), p1, accB[4*m+1]);                  \
                accB[4*m+2] = ffma2((HJB), p2, accB[4*m+2]);                  \
                accB[4*m+3] = ffma2((HJB), p3, accB[4*m+3]);                  \
            }                                                                 \
        }

        // --- fused: density k-group (4 hidden units) -> 4 Wc rows ---
        u64 sgA = 0ULL, sgB = 0ULL;
#pragma unroll
        for (int k = 0; k < 8; k++) {
            u64 w0a, w0b, w1a, w1b, w2a, w2b, ba, bb, sa, sb;
            lds16(base + O_W1R0 + k * 16, w0a, w0b);
            lds16(base + O_W1R1 + k * 16, w1a, w1b);
            lds16(base + O_W1R2 + k * 16, w2a, w2b);
            lds16(base + O_B1T  + k * 16, ba, bb);
            lds16(base + O_WSIG + k * 16, sa, sb);
            const u64 vA0 = relu2(ffma2(xxA, w0a, ffma2(yyA, w1a, ffma2(zzA, w2a, ba))));
            const u64 vA1 = relu2(ffma2(xxA, w0b, ffma2(yyA, w1b, ffma2(zzA, w2b, bb))));
            const u64 vB0 = relu2(ffma2(xxB, w0a, ffma2(yyB, w1a, ffma2(zzB, w2a, ba))));
            const u64 vB1 = relu2(ffma2(xxB, w0b, ffma2(yyB, w1b, ffma2(zzB, w2b, bb))));
            sgA = ffma2(vA0, sa, sgA); sgA = ffma2(vA1, sb, sgA);
            sgB = ffma2(vB0, sa, sgB); sgB = ffma2(vB1, sb, sgB);

            const float2 fA0 = up2(vA0), fA1 = up2(vA1);
            const float2 fB0 = up2(vB0), fB1 = up2(vB1);
            {
                const u64 hA0 = pk2(fA0.x, fA0.x), hB0 = pk2(fB0.x, fB0.x);
                WC_ROW(4 * k + 0, hA0, hB0)
            }
            {
                const u64 hA1 = pk2(fA0.y, fA0.y), hB1 = pk2(fB0.y, fB0.y);
                WC_ROW(4 * k + 1, hA1, hB1)
            }
            {
                const u64 hA2 = pk2(fA1.x, fA1.x), hB2 = pk2(fB1.x, fB1.x);
                WC_ROW(4 * k + 2, hA2, hB2)
            }
            {
                const u64 hA3 = pk2(fA1.y, fA1.y), hB3 = pk2(fB1.y, fB1.y);
                WC_ROW(4 * k + 3, hA3, hB3)
            }
        }
        WC_ROW(32, xxA, xxB)
        WC_ROW(33, yyA, yyB)
        WC_ROW(34, zzA, zzB)
#undef WC_ROW

        // --- sigma -> alpha ---
        const float2 sA2 = up2(sgA), sB2 = up2(sgB);
        const float sigA = sA2.x + sA2.y;
        const float sigB = sB2.x + sB2.y;
        const float sigmaA = fmaxf(sigA, 0.f) + __logf(1.f + __expf(-fabsf(sigA)));
        const float sigmaB = fmaxf(sigB, 0.f) + __logf(1.f + __expf(-fabsf(sigB)));
        const float deltaB = (sB == 511) ? (0.8f / 512.f) : ZSTEP;
        float qA = __expf(-ZSTEP  * sigmaA);
        float qB = __expf(-deltaB * sigmaB);
        const float alphaA = 1.f - qA;
        const float alphaB = 1.f - qB;
        qA += 1e-15f; qB += 1e-15f;

        // --- attr head: relu then @ Wa2 (both steps) ---
        u64 oA0 = 0ULL, oA1 = 0ULL, oB0 = 0ULL, oB1 = 0ULL;
#pragma unroll
        for (int k = 0; k < 8; k++) {
            u64 wa0, wa1v, wb0, wb1v;
            lds16(base + O_WA2A + k * 16, wa0, wa1v);
            lds16(base + O_WA2B + k * 16, wb0, wb1v);
            const u64 rA0 = relu2(accA[2*k+0]), rA1 = relu2(accA[2*k+1]);
            const u64 rB0 = relu2(accB[2*k+0]), rB1 = relu2(accB[2*k+1]);
            oA0 = ffma2(rA0, wa0, oA0); oA0 = ffma2(rA1, wa1v, oA0);
            oA1 = ffma2(rA0, wb0, oA1); oA1 = ffma2(rA1, wb1v, oA1);
            oB0 = ffma2(rB0, wa0, oB0); oB0 = ffma2(rB1, wa1v, oB0);
            oB1 = ffma2(rB0, wb0, oB1); oB1 = ffma2(rB1, wb1v, oB1);
        }
        const float2 tA0 = up2(oA0), tA1 = up2(oA1);
        const float2 tB0 = up2(oB0), tB1 = up2(oB1);
        const float aA0 = 1.f / (1.f + __expf(-(tA0.x + tA0.y)));
        const float aA1 = 1.f / (1.f + __expf(-(tA1.x + tA1.y)));
        const float aB0 = 1.f / (1.f + __expf(-(tB0.x + tB0.y)));
        const float aB1 = 1.f / (1.f + __expf(-(tB1.x + tB1.y)));

        // --- transmittance scans: steps A (s..s+31) then B (s+32..s+63) ---
        float PA = qA;
#pragma unroll
        for (int off = 1; off < 32; off <<= 1) {
            const float v = __shfl_up_sync(0xffffffffu, PA, off);
            if (lane >= off) PA *= v;
        }
        float PexA = __shfl_up_sync(0xffffffffu, PA, 1);
        if (lane == 0) PexA = 1.f;
        const float wA = alphaA * Tcarry * PexA;
        const float Tmid = Tcarry * __shfl_sync(0xffffffffu, PA, 31);

        float PB = qB;
#pragma unroll
        for (int off = 1; off < 32; off <<= 1) {
            const float v = __shfl_up_sync(0xffffffffu, PB, off);
            if (lane >= off) PB *= v;
        }
        float PexB = __shfl_up_sync(0xffffffffu, PB, 1);
        if (lane == 0) PexB = 1.f;
        const float wB = alphaB * Tmid * PexB;
        Tcarry = Tmid * __shfl_sync(0xffffffffu, PB, 31);

        depth = fmaf(wA, zA, fmaf(wB, zB, depth));
        img0  = fmaf(wA, aA0, fmaf(wB, aB0, img0));
        img1  = fmaf(wA, aA1, fmaf(wB, aB1, img1));
        wsum += wA + wB;
    }

    // warp reduction, lane 0 writes
#pragma unroll
    for (int off = 16; off; off >>= 1) {
        depth += __shfl_xor_sync(0xffffffffu, depth, off);
        img0  += __shfl_xor_sync(0xffffffffu, img0, off);
        img1  += __shfl_xor_sync(0xffffffffu, img1, off);
        wsum  += __shfl_xor_sync(0xffffffffu, wsum, off);
    }
    if (lane == 0) {
        out[ray]             = depth;        // depth        [N]
        out[N + ray * 2 + 0] = img0;         // image        [N,2]
        out[N + ray * 2 + 1] = img1;
        out[3 * N + ray]     = wsum;         // weights_sum  [N]
    }
}

// ---------------------------------------------------------------------------
// Launch. Inputs (metadata order):
// 0 rays_o  1 rays_d  2 time  3 W1  4 b1  5 Wsig  6 Wfeat  7 Wa1  8 ba1
// 9 Wa2  10 num_steps
// ---------------------------------------------------------------------------
extern "C" void kernel_launch(void* const* d_in, const int* in_sizes, int n_in,
                              void* d_out, int out_size) {
    const float* rays_o = (const float*)d_in[0];
    const float* rays_d = (const float*)d_in[1];
    const float* timep  = (const float*)d_in[2];
    const float* W1     = (const float*)d_in[3];
    const float* b1     = (const float*)d_in[4];
    const float* Wsig   = (const float*)d_in[5];
    const float* Wfeat  = (const float*)d_in[6];
    const float* Wa1    = (const float*)d_in[7];
    const float* ba1    = (const float*)d_in[8];
    const float* Wa2    = (const float*)d_in[9];

    const int N = in_sizes[0] / 3;   // 8192

    lidar_precompute_kernel<<<1, 1024>>>(W1, b1, timep, Wfeat, Wa1);
    lidar_render<<<(N + 3) / 4, 128>>>(rays_o, rays_d, W1, Wsig, Wa1,
                                       ba1, Wa2, (float*)d_out, N);
}